// round 10
// baseline (speedup 1.0000x reference)
#include <cuda_runtime.h>
#include <cuda_bf16.h>
#include <cstdint>

// Problem constants (B=4, H=16, N=4096, D=64, M2=512, N/M2=8)
#define B_H   64
#define SEQ   4096
#define DIM   64
#define M2C   512
#define SROW  80    // smem row stride in bf16; 160B stride -> conflict-free LDS.64 frags

// Scratch sketches in bf16, 1/8 scale pre-applied, contraction dim pair-interleaved:
// within each 16-elem k-group, pair p=(k>>1)&7 sits at phys pair 2*(p&3)+(p>>2),
// so a thread's (k=2t4, k=2t4+8) fragment pairs are adjacent -> one LDS.64.
__device__ __nv_bfloat16 g_sks[B_H * M2C * DIM];   // [bh][m'][a~]
__device__ __nv_bfloat16 g_stv[B_H * DIM * M2C];   // [bh][e][m'~]

__device__ __forceinline__ float ex2(float x) {
    float y; asm("ex2.approx.f32 %0, %1;" : "=f"(y) : "f"(x)); return y;
}
__device__ __forceinline__ uint32_t pack_bf2(float lo, float hi) {
    __nv_bfloat162 h = __floats2bfloat162_rn(lo, hi);
    return *(uint32_t*)&h;
}
__device__ __forceinline__ void mma_bf16(float c[4],
        uint32_t a0, uint32_t a1, uint32_t a2, uint32_t a3,
        uint32_t b0, uint32_t b1) {
    asm volatile(
        "mma.sync.aligned.m16n8k16.row.col.f32.bf16.bf16.f32 "
        "{%0,%1,%2,%3}, {%4,%5,%6,%7}, {%8,%9}, {%0,%1,%2,%3};\n"
        : "+f"(c[0]), "+f"(c[1]), "+f"(c[2]), "+f"(c[3])
        : "r"(a0), "r"(a1), "r"(a2), "r"(a3), "r"(b0), "r"(b1));
}
__device__ __forceinline__ void cpa16(uint32_t s, const void* g) {
    asm volatile("cp.async.cg.shared.global [%0], [%1], 16;" :: "r"(s), "l"(g));
}

// ---------------------------------------------------------------------------
// Kernel 1: build sketches, m' = r*64 + d permutation (softmax-invariant; the
// same permutation is applied to SKS and STV so the result is exact).
//   SKS_P[m'][a~] = (1/8) sum_j K[r*512 + j*64 + a][d]     (z = 0)
//   STV_P[e][m'~] = (1/8) sum_j V[(d*8+r)*8 + j][e]        (z = 1)
// Split across blockIdx.z so the two 64MB streams run concurrently.
// ---------------------------------------------------------------------------
__global__ __launch_bounds__(256) void sketch_kernel(const float* __restrict__ K,
                                                     const float* __restrict__ V) {
    __shared__ float acc[64 * 65];
    const int bh = blockIdx.x, r = blockIdx.y;
    const int tid = threadIdx.x;

    if (blockIdx.z == 0) {
        // --- SKS: acc[a][d] = sum_j K[r*512+j*64+a][d] ---
        const float* Kb = K + (size_t)bh * SEQ * DIM;
        __nv_bfloat16* sks = g_sks + (size_t)bh * M2C * DIM;
        for (int l = tid; l < 1024; l += 256) {
            int a = l >> 4, d4 = (l & 15) << 2;
            float4 s = make_float4(0.f, 0.f, 0.f, 0.f);
            #pragma unroll
            for (int j = 0; j < 8; j++) {
                float4 x = *(const float4*)&Kb[(r * 512 + j * 64 + a) * 64 + d4];
                s.x += x.x; s.y += x.y; s.z += x.z; s.w += x.w;
            }
            float* dst = &acc[a * 65 + d4];
            dst[0] = s.x; dst[1] = s.y; dst[2] = s.z; dst[3] = s.w;
        }
        __syncthreads();
        for (int l = tid; l < 2048; l += 256) {       // pair p covers a=2p,2p+1
            int d = l >> 5, p = l & 31;
            float lo = acc[(2 * p    ) * 65 + d] * 0.125f;
            float hi = acc[(2 * p + 1) * 65 + d] * 0.125f;
            int q = p & 7;
            int phys = ((p >> 3) << 4) + ((2 * (q & 3) + (q >> 2)) << 1);
            *(uint32_t*)&sks[(r * 64 + d) * 64 + phys] = pack_bf2(lo, hi);
        }
    } else {
        // --- STV: acc[d][e] = sum_j V[(d*8+r)*8+j][e] ---
        const float* Vb = V + (size_t)bh * SEQ * DIM;
        __nv_bfloat16* stv = g_stv + (size_t)bh * DIM * M2C;
        for (int l = tid; l < 1024; l += 256) {
            int d = l >> 4, e4 = (l & 15) << 2;
            float4 s = make_float4(0.f, 0.f, 0.f, 0.f);
            #pragma unroll
            for (int j = 0; j < 8; j++) {
                float4 x = *(const float4*)&Vb[((d * 8 + r) * 8 + j) * 64 + e4];
                s.x += x.x; s.y += x.y; s.z += x.z; s.w += x.w;
            }
            float* dst = &acc[d * 65 + e4];
            dst[0] = s.x; dst[1] = s.y; dst[2] = s.z; dst[3] = s.w;
        }
        __syncthreads();
        for (int l = tid; l < 2048; l += 256) {       // pair p covers d=2p,2p+1
            int e = l >> 5, p = l & 31;
            float lo = acc[(2 * p    ) * 65 + e] * 0.125f;
            float hi = acc[(2 * p + 1) * 65 + e] * 0.125f;
            int q = p & 7;
            int phys = ((p >> 3) << 4) + ((2 * (q & 3) + (q >> 2)) << 1);
            *(uint32_t*)&stv[e * 512 + r * 64 + phys] = pack_bf2(lo, hi);
        }
    }
}

// ---------------------------------------------------------------------------
// Kernel 2: out = softmax(Q SKS^T / 8) @ STV + V  via bf16 m16n8k16 mma.sync.
// 128 threads (4 warps); warp owns 32 query rows. 8 chunks of 64 sketch cols.
// 3-buffer cp.async ring with ONE barrier per chunk:
//   iter c: stage(c+1)->buf[(c+1)%3]; wait_group 1; barrier; compute buf[c%3].
// Safety: all warps pass barrier(c+1) only after finishing chunk c; buf[c%3]
// is next rewritten by stage(c+3), issued after barrier(c+1). P never leaves
// registers (GEMM1 C-frag pair == GEMM2 A-frag). exp via MUFU.EX2.
// ---------------------------------------------------------------------------
#define KVSZ (2 * 64 * SROW)    // one Ks+Vs buffer, in bf16 elems

__global__ __launch_bounds__(128, 3) void attn_kernel(const float* __restrict__ Q,
                                                      const float* __restrict__ V,
                                                      float* __restrict__ Out) {
    extern __shared__ __align__(16) char smb[];
    __nv_bfloat16* kvbuf = (__nv_bfloat16*)smb;              // [3][KVSZ]

    const int tid  = threadIdx.x;
    const int lane = tid & 31, warp = tid >> 5;
    const int g = lane >> 2, t4 = lane & 3;
    const int bh   = blockIdx.y;
    const int wrow = blockIdx.x * 128 + warp * 32;

    const float* Qb = Q + (size_t)bh * SEQ * DIM;
    const __nv_bfloat16* sksb = g_sks + (size_t)bh * M2C * DIM;
    const __nv_bfloat16* stvb = g_stv + (size_t)bh * DIM * M2C;

    auto stage = [&](int c, __nv_bfloat16* buf) {
        __nv_bfloat16* Kd = buf;
        __nv_bfloat16* Vd = buf + 64 * SROW;
        const int mc0 = c * 64;
        #pragma unroll
        for (int i = 0; i < 4; i++) {
            int l = tid + i * 128;
            int row = l >> 3, seg = (l & 7) * 8;
            cpa16((uint32_t)__cvta_generic_to_shared(&Kd[row * SROW + seg]),
                  &sksb[(mc0 + row) * 64 + seg]);
            cpa16((uint32_t)__cvta_generic_to_shared(&Vd[row * SROW + seg]),
                  &stvb[row * 512 + mc0 + seg]);
        }
        asm volatile("cp.async.commit_group;");
    };

    // Persistent Q fragments (both 16-row tiles); scale 0.125*log2(e) folded.
    const float qs = 0.125f * 1.4426950408889634f;
    uint32_t Qa[4][8];
    #pragma unroll
    for (int tt = 0; tt < 2; tt++) {
        const float* q0 = Qb + (size_t)(wrow + tt * 16 + g) * DIM;
        const float* q1 = Qb + (size_t)(wrow + tt * 16 + g + 8) * DIM;
        #pragma unroll
        for (int kk = 0; kk < 4; kk++) {
            float2 x0 = *(const float2*)&q0[kk * 16 + 2 * t4];
            float2 x1 = *(const float2*)&q1[kk * 16 + 2 * t4];
            float2 x2 = *(const float2*)&q0[kk * 16 + 2 * t4 + 8];
            float2 x3 = *(const float2*)&q1[kk * 16 + 2 * t4 + 8];
            Qa[kk][tt * 4 + 0] = pack_bf2(x0.x * qs, x0.y * qs);
            Qa[kk][tt * 4 + 1] = pack_bf2(x1.x * qs, x1.y * qs);
            Qa[kk][tt * 4 + 2] = pack_bf2(x2.x * qs, x2.y * qs);
            Qa[kk][tt * 4 + 3] = pack_bf2(x3.x * qs, x3.y * qs);
        }
    }

    float O0[8][4], O1[8][4];
    #pragma unroll
    for (int j = 0; j < 8; j++)
        #pragma unroll
        for (int c = 0; c < 4; c++) { O0[j][c] = 0.f; O1[j][c] = 0.f; }
    float sum0 = 0.f, sum1 = 0.f, sum2 = 0.f, sum3 = 0.f;

    stage(0, kvbuf);    // prologue: chunk 0 -> buffer 0

    #pragma unroll
    for (int c = 0; c < 8; c++) {
        __nv_bfloat16* Ks = kvbuf + (c % 3) * KVSZ;
        __nv_bfloat16* Vs = Ks + 64 * SROW;

        if (c + 1 < 8) {
            stage(c + 1, kvbuf + ((c + 1) % 3) * KVSZ);
            asm volatile("cp.async.wait_group 1;");
        } else {
            asm volatile("cp.async.wait_group 0;");
        }
        __syncthreads();   // single rendezvous per chunk

        const __nv_bfloat16* KsW = Ks + g * SROW + 4 * t4;   // hoisted frag bases
        const __nv_bfloat16* VsW = Vs + g * SROW + 4 * t4;

        #pragma unroll
        for (int jj = 0; jj < 4; jj++) {
            // ---- GEMM1: logits for j-pair (2jj, 2jj+1), both 16-row tiles ----
            float Sa[4] = {0,0,0,0}, Sb[4] = {0,0,0,0};   // tile0/tile1, col j0
            float Sc[4] = {0,0,0,0}, Sd[4] = {0,0,0,0};   // tile0/tile1, col j1
            #pragma unroll
            for (int kk = 0; kk < 4; kk++) {
                uint2 Bx = *(const uint2*)&KsW[(2 * jj    ) * 8 * SROW + kk * 16];
                uint2 By = *(const uint2*)&KsW[(2 * jj + 1) * 8 * SROW + kk * 16];
                mma_bf16(Sa, Qa[kk][0], Qa[kk][1], Qa[kk][2], Qa[kk][3], Bx.x, Bx.y);
                mma_bf16(Sb, Qa[kk][4], Qa[kk][5], Qa[kk][6], Qa[kk][7], Bx.x, Bx.y);
                mma_bf16(Sc, Qa[kk][0], Qa[kk][1], Qa[kk][2], Qa[kk][3], By.x, By.y);
                mma_bf16(Sd, Qa[kk][4], Qa[kk][5], Qa[kk][6], Qa[kk][7], By.x, By.y);
            }
            // ---- exp + pack: C-frag (j0,j1) == A-frag of GEMM2 k-group jj ----
            float pa0 = ex2(Sa[0]), pa1 = ex2(Sa[1]), pa2 = ex2(Sa[2]), pa3 = ex2(Sa[3]);
            float pb0 = ex2(Sb[0]), pb1 = ex2(Sb[1]), pb2 = ex2(Sb[2]), pb3 = ex2(Sb[3]);
            float pc0 = ex2(Sc[0]), pc1 = ex2(Sc[1]), pc2 = ex2(Sc[2]), pc3 = ex2(Sc[3]);
            float pd0 = ex2(Sd[0]), pd1 = ex2(Sd[1]), pd2 = ex2(Sd[2]), pd3 = ex2(Sd[3]);
            sum0 += pa0 + pa1 + pc0 + pc1;     // tile0 row g
            sum1 += pa2 + pa3 + pc2 + pc3;     // tile0 row g+8
            sum2 += pb0 + pb1 + pd0 + pd1;     // tile1 row g
            sum3 += pb2 + pb3 + pd2 + pd3;     // tile1 row g+8
            uint32_t a0 = pack_bf2(pa0, pa1), a1 = pack_bf2(pa2, pa3);
            uint32_t a2 = pack_bf2(pc0, pc1), a3 = pack_bf2(pc2, pc3);
            uint32_t a4 = pack_bf2(pb0, pb1), a5 = pack_bf2(pb2, pb3);
            uint32_t a6 = pack_bf2(pd0, pd1), a7 = pack_bf2(pd2, pd3);
            // ---- GEMM2 partial: O += P(:, kk=jj) @ STV(kk=jj, :) ----
            #pragma unroll
            for (int j = 0; j < 8; j++) {
                uint2 Bv = *(const uint2*)&VsW[j * 8 * SROW + jj * 16];
                mma_bf16(O0[j], a0, a1, a2, a3, Bv.x, Bv.y);
                mma_bf16(O1[j], a4, a5, a6, a7, Bv.x, Bv.y);
            }
        }
    }

    // quad-reduce row sums (lanes 4g..4g+3 share rows)
    sum0 += __shfl_xor_sync(0xffffffffu, sum0, 1);
    sum0 += __shfl_xor_sync(0xffffffffu, sum0, 2);
    sum1 += __shfl_xor_sync(0xffffffffu, sum1, 1);
    sum1 += __shfl_xor_sync(0xffffffffu, sum1, 2);
    sum2 += __shfl_xor_sync(0xffffffffu, sum2, 1);
    sum2 += __shfl_xor_sync(0xffffffffu, sum2, 2);
    sum3 += __shfl_xor_sync(0xffffffffu, sum3, 1);
    sum3 += __shfl_xor_sync(0xffffffffu, sum3, 2);
    const float i0 = 1.f / sum0, i1 = 1.f / sum1, i2 = 1.f / sum2, i3 = 1.f / sum3;

    const float* Vb = V + (size_t)bh * SEQ * DIM;
    float* Ob = Out + (size_t)bh * SEQ * DIM;
    const size_t r0 = wrow + g, r1 = r0 + 8, r2 = r0 + 16, r3 = r0 + 24;
    #pragma unroll
    for (int j = 0; j < 8; j++) {
        int cix = j * 8 + 2 * t4;
        float2 v0 = *(const float2*)&Vb[r0 * DIM + cix];
        float2 v1 = *(const float2*)&Vb[r1 * DIM + cix];
        float2 v2 = *(const float2*)&Vb[r2 * DIM + cix];
        float2 v3 = *(const float2*)&Vb[r3 * DIM + cix];
        *(float2*)&Ob[r0 * DIM + cix] = make_float2(O0[j][0] * i0 + v0.x, O0[j][1] * i0 + v0.y);
        *(float2*)&Ob[r1 * DIM + cix] = make_float2(O0[j][2] * i1 + v1.x, O0[j][3] * i1 + v1.y);
        *(float2*)&Ob[r2 * DIM + cix] = make_float2(O1[j][0] * i2 + v2.x, O1[j][1] * i2 + v2.y);
        *(float2*)&Ob[r3 * DIM + cix] = make_float2(O1[j][2] * i3 + v3.x, O1[j][3] * i3 + v3.y);
    }
}

extern "C" void kernel_launch(void* const* d_in, const int* in_sizes, int n_in,
                              void* d_out, int out_size) {
    const float* Q = (const float*)d_in[0];
    const float* K = (const float*)d_in[1];
    const float* V = (const float*)d_in[2];
    float*       O = (float*)d_out;

    const int smem = 3 * KVSZ * (int)sizeof(__nv_bfloat16);   // 61440 B
    cudaFuncSetAttribute(attn_kernel, cudaFuncAttributeMaxDynamicSharedMemorySize, smem);

    sketch_kernel<<<dim3(B_H, 8, 2), 256>>>(K, V);
    attn_kernel<<<dim3(SEQ / 128, B_H), 128, smem>>>(Q, V, O);
}

// round 15
// speedup vs baseline: 1.0158x; 1.0158x over previous
#include <cuda_runtime.h>
#include <cuda_bf16.h>
#include <cstdint>

// Problem constants (B=4, H=16, N=4096, D=64, M2=512, N/M2=8)
#define B_H   64
#define SEQ   4096
#define DIM   64
#define M2C   512
#define SROW  80    // smem row stride in bf16; 160B stride -> conflict-free LDS.64 frags

// Scratch sketches in bf16, 1/8 scale pre-applied, contraction dim pair-interleaved:
// within each 16-elem k-group, pair p=(k>>1)&7 sits at phys pair 2*(p&3)+(p>>2),
// so a thread's (k=2t4, k=2t4+8) fragment pairs are adjacent -> one LDS.64.
__device__ __nv_bfloat16 g_sks[B_H * M2C * DIM];   // [bh][m'][a~]
__device__ __nv_bfloat16 g_stv[B_H * DIM * M2C];   // [bh][e][m'~]

__device__ __forceinline__ float ex2(float x) {
    float y; asm("ex2.approx.f32 %0, %1;" : "=f"(y) : "f"(x)); return y;
}
__device__ __forceinline__ uint32_t pack_bf2(float lo, float hi) {
    __nv_bfloat162 h = __floats2bfloat162_rn(lo, hi);
    return *(uint32_t*)&h;
}
__device__ __forceinline__ void mma_bf16(float c[4],
        uint32_t a0, uint32_t a1, uint32_t a2, uint32_t a3,
        uint32_t b0, uint32_t b1) {
    asm volatile(
        "mma.sync.aligned.m16n8k16.row.col.f32.bf16.bf16.f32 "
        "{%0,%1,%2,%3}, {%4,%5,%6,%7}, {%8,%9}, {%0,%1,%2,%3};\n"
        : "+f"(c[0]), "+f"(c[1]), "+f"(c[2]), "+f"(c[3])
        : "r"(a0), "r"(a1), "r"(a2), "r"(a3), "r"(b0), "r"(b1));
}
__device__ __forceinline__ void cpa16(uint32_t s, const void* g) {
    asm volatile("cp.async.cg.shared.global [%0], [%1], 16;" :: "r"(s), "l"(g));
}

// ---------------------------------------------------------------------------
// Kernel 1: build sketches, m' = r*64 + d permutation (softmax-invariant; the
// same permutation is applied to SKS and STV so the result is exact).
//   SKS_P[m'][a~] = (1/8) sum_j K[r*512 + j*64 + a][d]     (z = 0)
//   STV_P[e][m'~] = (1/8) sum_j V[(d*8+r)*8 + j][e]        (z = 1)
// Split across blockIdx.z so the two 64MB streams run concurrently.
// ---------------------------------------------------------------------------
__global__ __launch_bounds__(256) void sketch_kernel(const float* __restrict__ K,
                                                     const float* __restrict__ V) {
    __shared__ float acc[64 * 65];
    const int bh = blockIdx.x, r = blockIdx.y;
    const int tid = threadIdx.x;

    if (blockIdx.z == 0) {
        const float* Kb = K + (size_t)bh * SEQ * DIM;
        __nv_bfloat16* sks = g_sks + (size_t)bh * M2C * DIM;
        for (int l = tid; l < 1024; l += 256) {
            int a = l >> 4, d4 = (l & 15) << 2;
            float4 s = make_float4(0.f, 0.f, 0.f, 0.f);
            #pragma unroll
            for (int j = 0; j < 8; j++) {
                float4 x = *(const float4*)&Kb[(r * 512 + j * 64 + a) * 64 + d4];
                s.x += x.x; s.y += x.y; s.z += x.z; s.w += x.w;
            }
            float* dst = &acc[a * 65 + d4];
            dst[0] = s.x; dst[1] = s.y; dst[2] = s.z; dst[3] = s.w;
        }
        __syncthreads();
        for (int l = tid; l < 2048; l += 256) {       // pair p covers a=2p,2p+1
            int d = l >> 5, p = l & 31;
            float lo = acc[(2 * p    ) * 65 + d] * 0.125f;
            float hi = acc[(2 * p + 1) * 65 + d] * 0.125f;
            int q = p & 7;
            int phys = ((p >> 3) << 4) + ((2 * (q & 3) + (q >> 2)) << 1);
            *(uint32_t*)&sks[(r * 64 + d) * 64 + phys] = pack_bf2(lo, hi);
        }
    } else {
        const float* Vb = V + (size_t)bh * SEQ * DIM;
        __nv_bfloat16* stv = g_stv + (size_t)bh * DIM * M2C;
        for (int l = tid; l < 1024; l += 256) {
            int d = l >> 4, e4 = (l & 15) << 2;
            float4 s = make_float4(0.f, 0.f, 0.f, 0.f);
            #pragma unroll
            for (int j = 0; j < 8; j++) {
                float4 x = *(const float4*)&Vb[((d * 8 + r) * 8 + j) * 64 + e4];
                s.x += x.x; s.y += x.y; s.z += x.z; s.w += x.w;
            }
            float* dst = &acc[d * 65 + e4];
            dst[0] = s.x; dst[1] = s.y; dst[2] = s.z; dst[3] = s.w;
        }
        __syncthreads();
        for (int l = tid; l < 2048; l += 256) {       // pair p covers d=2p,2p+1
            int e = l >> 5, p = l & 31;
            float lo = acc[(2 * p    ) * 65 + e] * 0.125f;
            float hi = acc[(2 * p + 1) * 65 + e] * 0.125f;
            int q = p & 7;
            int phys = ((p >> 3) << 4) + ((2 * (q & 3) + (q >> 2)) << 1);
            *(uint32_t*)&stv[e * 512 + r * 64 + phys] = pack_bf2(lo, hi);
        }
    }
}

// ---------------------------------------------------------------------------
// Kernel 2: out = softmax(Q SKS^T / 8) @ STV + V  via bf16 m16n8k16 mma.sync.
// 128 threads (4 warps); warp owns 32 query rows. 8 chunks of 64 sketch cols,
// double-buffered cp.async pipeline (R8 structure, best measured). P never
// leaves registers (GEMM1 C-frag pair == GEMM2 A-frag of k-group jj).
// exp via MUFU.EX2 (log2e/8 folded into Q).
// __launch_bounds__(128, 4): cap regs at 128 -> 16 warps/SM (was 12 at 168r).
// ---------------------------------------------------------------------------
#define KVSZ (2 * 64 * SROW)    // one Ks+Vs buffer, in bf16 elems

__global__ __launch_bounds__(128, 4) void attn_kernel(const float* __restrict__ Q,
                                                      const float* __restrict__ V,
                                                      float* __restrict__ Out) {
    extern __shared__ __align__(16) char smb[];
    __nv_bfloat16* kvbuf = (__nv_bfloat16*)smb;              // [2][KVSZ]

    const int tid  = threadIdx.x;
    const int lane = tid & 31, warp = tid >> 5;
    const int g = lane >> 2, t4 = lane & 3;
    const int bh   = blockIdx.y;
    const int wrow = blockIdx.x * 128 + warp * 32;

    const float* Qb = Q + (size_t)bh * SEQ * DIM;
    const __nv_bfloat16* sksb = g_sks + (size_t)bh * M2C * DIM;
    const __nv_bfloat16* stvb = g_stv + (size_t)bh * DIM * M2C;

    auto stage = [&](int c, __nv_bfloat16* buf) {
        __nv_bfloat16* Kd = buf;
        __nv_bfloat16* Vd = buf + 64 * SROW;
        const int mc0 = c * 64;
        #pragma unroll
        for (int i = 0; i < 4; i++) {
            int l = tid + i * 128;
            int row = l >> 3, seg = (l & 7) * 8;
            cpa16((uint32_t)__cvta_generic_to_shared(&Kd[row * SROW + seg]),
                  &sksb[(mc0 + row) * 64 + seg]);
            cpa16((uint32_t)__cvta_generic_to_shared(&Vd[row * SROW + seg]),
                  &stvb[row * 512 + mc0 + seg]);
        }
        asm volatile("cp.async.commit_group;");
    };

    // Persistent Q fragments (both 16-row tiles); scale 0.125*log2(e) folded.
    const float qs = 0.125f * 1.4426950408889634f;
    uint32_t Qa[4][8];
    #pragma unroll
    for (int tt = 0; tt < 2; tt++) {
        const float* q0 = Qb + (size_t)(wrow + tt * 16 + g) * DIM;
        const float* q1 = Qb + (size_t)(wrow + tt * 16 + g + 8) * DIM;
        #pragma unroll
        for (int kk = 0; kk < 4; kk++) {
            float2 x0 = *(const float2*)&q0[kk * 16 + 2 * t4];
            float2 x1 = *(const float2*)&q1[kk * 16 + 2 * t4];
            float2 x2 = *(const float2*)&q0[kk * 16 + 2 * t4 + 8];
            float2 x3 = *(const float2*)&q1[kk * 16 + 2 * t4 + 8];
            Qa[kk][tt * 4 + 0] = pack_bf2(x0.x * qs, x0.y * qs);
            Qa[kk][tt * 4 + 1] = pack_bf2(x1.x * qs, x1.y * qs);
            Qa[kk][tt * 4 + 2] = pack_bf2(x2.x * qs, x2.y * qs);
            Qa[kk][tt * 4 + 3] = pack_bf2(x3.x * qs, x3.y * qs);
        }
    }

    float O0[8][4], O1[8][4];
    #pragma unroll
    for (int j = 0; j < 8; j++)
        #pragma unroll
        for (int c = 0; c < 4; c++) { O0[j][c] = 0.f; O1[j][c] = 0.f; }
    float sum0 = 0.f, sum1 = 0.f, sum2 = 0.f, sum3 = 0.f;

    stage(0, kvbuf);    // prologue: chunk 0 -> buffer 0

    for (int c = 0; c < 8; c++) {
        __nv_bfloat16* Ks = kvbuf + (c & 1) * KVSZ;
        __nv_bfloat16* Vs = Ks + 64 * SROW;

        if (c + 1 < 8) {
            stage(c + 1, kvbuf + ((c + 1) & 1) * KVSZ);
            asm volatile("cp.async.wait_group 1;");
        } else {
            asm volatile("cp.async.wait_group 0;");
        }
        __syncthreads();   // chunk-c tiles visible to all warps

        const __nv_bfloat16* KsW = Ks + g * SROW + 4 * t4;   // hoisted frag bases
        const __nv_bfloat16* VsW = Vs + g * SROW + 4 * t4;

        #pragma unroll
        for (int jj = 0; jj < 4; jj++) {
            // ---- GEMM1: logits for j-pair (2jj, 2jj+1), both 16-row tiles ----
            float Sa[4] = {0,0,0,0}, Sb[4] = {0,0,0,0};   // tile0/tile1, col j0
            float Sc[4] = {0,0,0,0}, Sd[4] = {0,0,0,0};   // tile0/tile1, col j1
            #pragma unroll
            for (int kk = 0; kk < 4; kk++) {
                uint2 Bx = *(const uint2*)&KsW[(2 * jj    ) * 8 * SROW + kk * 16];
                uint2 By = *(const uint2*)&KsW[(2 * jj + 1) * 8 * SROW + kk * 16];
                mma_bf16(Sa, Qa[kk][0], Qa[kk][1], Qa[kk][2], Qa[kk][3], Bx.x, Bx.y);
                mma_bf16(Sb, Qa[kk][4], Qa[kk][5], Qa[kk][6], Qa[kk][7], Bx.x, Bx.y);
                mma_bf16(Sc, Qa[kk][0], Qa[kk][1], Qa[kk][2], Qa[kk][3], By.x, By.y);
                mma_bf16(Sd, Qa[kk][4], Qa[kk][5], Qa[kk][6], Qa[kk][7], By.x, By.y);
            }
            // ---- exp (in place) + pack: C-frag (j0,j1) == A-frag of GEMM2 jj ----
            #pragma unroll
            for (int u = 0; u < 4; u++) {
                Sa[u] = ex2(Sa[u]); Sb[u] = ex2(Sb[u]);
                Sc[u] = ex2(Sc[u]); Sd[u] = ex2(Sd[u]);
            }
            sum0 += Sa[0] + Sa[1] + Sc[0] + Sc[1];     // tile0 row g
            sum1 += Sa[2] + Sa[3] + Sc[2] + Sc[3];     // tile0 row g+8
            sum2 += Sb[0] + Sb[1] + Sd[0] + Sd[1];     // tile1 row g
            sum3 += Sb[2] + Sb[3] + Sd[2] + Sd[3];     // tile1 row g+8
            uint32_t a0 = pack_bf2(Sa[0], Sa[1]), a1 = pack_bf2(Sa[2], Sa[3]);
            uint32_t a2 = pack_bf2(Sc[0], Sc[1]), a3 = pack_bf2(Sc[2], Sc[3]);
            uint32_t a4 = pack_bf2(Sb[0], Sb[1]), a5 = pack_bf2(Sb[2], Sb[3]);
            uint32_t a6 = pack_bf2(Sd[0], Sd[1]), a7 = pack_bf2(Sd[2], Sd[3]);
            // ---- GEMM2 partial: O += P(:, kk=jj) @ STV(kk=jj, :) ----
            #pragma unroll
            for (int j = 0; j < 8; j++) {
                uint2 Bv = *(const uint2*)&VsW[j * 8 * SROW + jj * 16];
                mma_bf16(O0[j], a0, a1, a2, a3, Bv.x, Bv.y);
                mma_bf16(O1[j], a4, a5, a6, a7, Bv.x, Bv.y);
            }
        }
        __syncthreads();   // all warps done reading chunk-c tiles
    }

    // quad-reduce row sums (lanes 4g..4g+3 share rows)
    sum0 += __shfl_xor_sync(0xffffffffu, sum0, 1);
    sum0 += __shfl_xor_sync(0xffffffffu, sum0, 2);
    sum1 += __shfl_xor_sync(0xffffffffu, sum1, 1);
    sum1 += __shfl_xor_sync(0xffffffffu, sum1, 2);
    sum2 += __shfl_xor_sync(0xffffffffu, sum2, 1);
    sum2 += __shfl_xor_sync(0xffffffffu, sum2, 2);
    sum3 += __shfl_xor_sync(0xffffffffu, sum3, 1);
    sum3 += __shfl_xor_sync(0xffffffffu, sum3, 2);
    const float i0 = 1.f / sum0, i1 = 1.f / sum1, i2 = 1.f / sum2, i3 = 1.f / sum3;

    const float* Vb = V + (size_t)bh * SEQ * DIM;
    float* Ob = Out + (size_t)bh * SEQ * DIM;
    const size_t r0 = wrow + g, r1 = r0 + 8, r2 = r0 + 16, r3 = r0 + 24;
    #pragma unroll
    for (int j = 0; j < 8; j++) {
        int cix = j * 8 + 2 * t4;
        float2 v0 = *(const float2*)&Vb[r0 * DIM + cix];
        float2 v1 = *(const float2*)&Vb[r1 * DIM + cix];
        float2 v2 = *(const float2*)&Vb[r2 * DIM + cix];
        float2 v3 = *(const float2*)&Vb[r3 * DIM + cix];
        *(float2*)&Ob[r0 * DIM + cix] = make_float2(O0[j][0] * i0 + v0.x, O0[j][1] * i0 + v0.y);
        *(float2*)&Ob[r1 * DIM + cix] = make_float2(O0[j][2] * i1 + v1.x, O0[j][3] * i1 + v1.y);
        *(float2*)&Ob[r2 * DIM + cix] = make_float2(O1[j][0] * i2 + v2.x, O1[j][1] * i2 + v2.y);
        *(float2*)&Ob[r3 * DIM + cix] = make_float2(O1[j][2] * i3 + v3.x, O1[j][3] * i3 + v3.y);
    }
}

extern "C" void kernel_launch(void* const* d_in, const int* in_sizes, int n_in,
                              void* d_out, int out_size) {
    const float* Q = (const float*)d_in[0];
    const float* K = (const float*)d_in[1];
    const float* V = (const float*)d_in[2];
    float*       O = (float*)d_out;

    const int smem = 2 * KVSZ * (int)sizeof(__nv_bfloat16);   // 40960 B
    cudaFuncSetAttribute(attn_kernel, cudaFuncAttributeMaxDynamicSharedMemorySize, smem);

    sketch_kernel<<<dim3(B_H, 8, 2), 256>>>(K, V);
    attn_kernel<<<dim3(SEQ / 128, B_H), 128, smem>>>(Q, V, O);
}

// round 16
// speedup vs baseline: 1.0160x; 1.0002x over previous
#include <cuda_runtime.h>
#include <cuda_bf16.h>
#include <cstdint>

// Problem constants (B=4, H=16, N=4096, D=64, M2=512, N/M2=8)
#define B_H   64
#define SEQ   4096
#define DIM   64
#define M2C   512
#define SROW  80    // smem row stride in bf16; 160B stride -> conflict-free LDS.64 frags

// Scratch sketches in bf16, 1/8 scale pre-applied, contraction dim pair-interleaved:
// within each 16-elem k-group, pair p=(k>>1)&7 sits at phys pair 2*(p&3)+(p>>2),
// so a thread's (k=2t4, k=2t4+8) fragment pairs are adjacent -> one LDS.64.
__device__ __nv_bfloat16 g_sks[B_H * M2C * DIM];   // [bh][m'][a~]
__device__ __nv_bfloat16 g_stv[B_H * DIM * M2C];   // [bh][e][m'~]

__device__ __forceinline__ float ex2(float x) {
    float y; asm("ex2.approx.f32 %0, %1;" : "=f"(y) : "f"(x)); return y;
}
__device__ __forceinline__ uint32_t pack_bf2(float lo, float hi) {
    __nv_bfloat162 h = __floats2bfloat162_rn(lo, hi);
    return *(uint32_t*)&h;
}
__device__ __forceinline__ void mma_bf16(float c[4],
        uint32_t a0, uint32_t a1, uint32_t a2, uint32_t a3,
        uint32_t b0, uint32_t b1) {
    asm volatile(
        "mma.sync.aligned.m16n8k16.row.col.f32.bf16.bf16.f32 "
        "{%0,%1,%2,%3}, {%4,%5,%6,%7}, {%8,%9}, {%0,%1,%2,%3};\n"
        : "+f"(c[0]), "+f"(c[1]), "+f"(c[2]), "+f"(c[3])
        : "r"(a0), "r"(a1), "r"(a2), "r"(a3), "r"(b0), "r"(b1));
}
__device__ __forceinline__ void cpa16(uint32_t s, const void* g) {
    asm volatile("cp.async.cg.shared.global [%0], [%1], 16;" :: "r"(s), "l"(g));
}

// ---------------------------------------------------------------------------
// Kernel 1: build sketches, m' = r*64 + d permutation (softmax-invariant; the
// same permutation is applied to SKS and STV so the result is exact).
//   SKS_P[m'][a~] = (1/8) sum_j K[r*512 + j*64 + a][d]     (z = 0)
//   STV_P[e][m'~] = (1/8) sum_j V[(d*8+r)*8 + j][e]        (z = 1)
// Split across blockIdx.z so the two 64MB streams run concurrently.
// ---------------------------------------------------------------------------
__global__ __launch_bounds__(256) void sketch_kernel(const float* __restrict__ K,
                                                     const float* __restrict__ V) {
    __shared__ float acc[64 * 65];
    const int bh = blockIdx.x, r = blockIdx.y;
    const int tid = threadIdx.x;

    if (blockIdx.z == 0) {
        const float* Kb = K + (size_t)bh * SEQ * DIM;
        __nv_bfloat16* sks = g_sks + (size_t)bh * M2C * DIM;
        for (int l = tid; l < 1024; l += 256) {
            int a = l >> 4, d4 = (l & 15) << 2;
            float4 s = make_float4(0.f, 0.f, 0.f, 0.f);
            #pragma unroll
            for (int j = 0; j < 8; j++) {
                float4 x = *(const float4*)&Kb[(r * 512 + j * 64 + a) * 64 + d4];
                s.x += x.x; s.y += x.y; s.z += x.z; s.w += x.w;
            }
            float* dst = &acc[a * 65 + d4];
            dst[0] = s.x; dst[1] = s.y; dst[2] = s.z; dst[3] = s.w;
        }
        __syncthreads();
        for (int l = tid; l < 2048; l += 256) {       // pair p covers a=2p,2p+1
            int d = l >> 5, p = l & 31;
            float lo = acc[(2 * p    ) * 65 + d] * 0.125f;
            float hi = acc[(2 * p + 1) * 65 + d] * 0.125f;
            int q = p & 7;
            int phys = ((p >> 3) << 4) + ((2 * (q & 3) + (q >> 2)) << 1);
            *(uint32_t*)&sks[(r * 64 + d) * 64 + phys] = pack_bf2(lo, hi);
        }
    } else {
        const float* Vb = V + (size_t)bh * SEQ * DIM;
        __nv_bfloat16* stv = g_stv + (size_t)bh * DIM * M2C;
        for (int l = tid; l < 1024; l += 256) {
            int d = l >> 4, e4 = (l & 15) << 2;
            float4 s = make_float4(0.f, 0.f, 0.f, 0.f);
            #pragma unroll
            for (int j = 0; j < 8; j++) {
                float4 x = *(const float4*)&Vb[((d * 8 + r) * 8 + j) * 64 + e4];
                s.x += x.x; s.y += x.y; s.z += x.z; s.w += x.w;
            }
            float* dst = &acc[d * 65 + e4];
            dst[0] = s.x; dst[1] = s.y; dst[2] = s.z; dst[3] = s.w;
        }
        __syncthreads();
        for (int l = tid; l < 2048; l += 256) {       // pair p covers d=2p,2p+1
            int e = l >> 5, p = l & 31;
            float lo = acc[(2 * p    ) * 65 + e] * 0.125f;
            float hi = acc[(2 * p + 1) * 65 + e] * 0.125f;
            int q = p & 7;
            int phys = ((p >> 3) << 4) + ((2 * (q & 3) + (q >> 2)) << 1);
            *(uint32_t*)&stv[e * 512 + r * 64 + phys] = pack_bf2(lo, hi);
        }
    }
}

// ---------------------------------------------------------------------------
// Kernel 2: out = softmax(Q SKS^T / 8) @ STV + V  via bf16 m16n8k16 mma.sync.
// 128 threads (4 warps); warp owns 32 query rows. 8 chunks of 64 sketch cols,
// double-buffered cp.async pipeline. P never leaves registers (GEMM1 C-frag
// pair == GEMM2 A-frag of k-group jj). Software-pipelined inner loop:
// GEMM1(jj+1) issues INTERLEAVED with GEMM2(jj), merging a 4-chain and a
// 16-chain MMA block into one 20-chain block -> HMMA RAW latency covered.
// exp via MUFU.EX2 (log2e/8 folded into Q).
// ---------------------------------------------------------------------------
#define KVSZ (2 * 64 * SROW)    // one Ks+Vs buffer, in bf16 elems

__global__ __launch_bounds__(128, 3) void attn_kernel(const float* __restrict__ Q,
                                                      const float* __restrict__ V,
                                                      float* __restrict__ Out) {
    extern __shared__ __align__(16) char smb[];
    __nv_bfloat16* kvbuf = (__nv_bfloat16*)smb;              // [2][KVSZ]

    const int tid  = threadIdx.x;
    const int lane = tid & 31, warp = tid >> 5;
    const int g = lane >> 2, t4 = lane & 3;
    const int bh   = blockIdx.y;
    const int wrow = blockIdx.x * 128 + warp * 32;

    const float* Qb = Q + (size_t)bh * SEQ * DIM;
    const __nv_bfloat16* sksb = g_sks + (size_t)bh * M2C * DIM;
    const __nv_bfloat16* stvb = g_stv + (size_t)bh * DIM * M2C;

    auto stage = [&](int c, __nv_bfloat16* buf) {
        __nv_bfloat16* Kd = buf;
        __nv_bfloat16* Vd = buf + 64 * SROW;
        const int mc0 = c * 64;
        #pragma unroll
        for (int i = 0; i < 4; i++) {
            int l = tid + i * 128;
            int row = l >> 3, seg = (l & 7) * 8;
            cpa16((uint32_t)__cvta_generic_to_shared(&Kd[row * SROW + seg]),
                  &sksb[(mc0 + row) * 64 + seg]);
            cpa16((uint32_t)__cvta_generic_to_shared(&Vd[row * SROW + seg]),
                  &stvb[row * 512 + mc0 + seg]);
        }
        asm volatile("cp.async.commit_group;");
    };

    // Persistent Q fragments (both 16-row tiles); scale 0.125*log2(e) folded.
    const float qs = 0.125f * 1.4426950408889634f;
    uint32_t Qa[4][8];
    #pragma unroll
    for (int tt = 0; tt < 2; tt++) {
        const float* q0 = Qb + (size_t)(wrow + tt * 16 + g) * DIM;
        const float* q1 = Qb + (size_t)(wrow + tt * 16 + g + 8) * DIM;
        #pragma unroll
        for (int kk = 0; kk < 4; kk++) {
            float2 x0 = *(const float2*)&q0[kk * 16 + 2 * t4];
            float2 x1 = *(const float2*)&q1[kk * 16 + 2 * t4];
            float2 x2 = *(const float2*)&q0[kk * 16 + 2 * t4 + 8];
            float2 x3 = *(const float2*)&q1[kk * 16 + 2 * t4 + 8];
            Qa[kk][tt * 4 + 0] = pack_bf2(x0.x * qs, x0.y * qs);
            Qa[kk][tt * 4 + 1] = pack_bf2(x1.x * qs, x1.y * qs);
            Qa[kk][tt * 4 + 2] = pack_bf2(x2.x * qs, x2.y * qs);
            Qa[kk][tt * 4 + 3] = pack_bf2(x3.x * qs, x3.y * qs);
        }
    }

    float O0[8][4], O1[8][4];
    #pragma unroll
    for (int j = 0; j < 8; j++)
        #pragma unroll
        for (int c = 0; c < 4; c++) { O0[j][c] = 0.f; O1[j][c] = 0.f; }
    float sum0 = 0.f, sum1 = 0.f, sum2 = 0.f, sum3 = 0.f;

    stage(0, kvbuf);    // prologue: chunk 0 -> buffer 0

    for (int c = 0; c < 8; c++) {
        __nv_bfloat16* Ks = kvbuf + (c & 1) * KVSZ;
        __nv_bfloat16* Vs = Ks + 64 * SROW;

        if (c + 1 < 8) {
            stage(c + 1, kvbuf + ((c + 1) & 1) * KVSZ);
            asm volatile("cp.async.wait_group 1;");
        } else {
            asm volatile("cp.async.wait_group 0;");
        }
        __syncthreads();   // chunk-c tiles visible to all warps

        const __nv_bfloat16* KsW = Ks + g * SROW + 4 * t4;   // hoisted frag bases
        const __nv_bfloat16* VsW = Vs + g * SROW + 4 * t4;

        // Scur/Snxt: [0]=tile0 col j0, [1]=tile1 col j0, [2]=tile0 j1, [3]=tile1 j1
        float Scur[4][4], Snxt[4][4];

        // --- prologue: GEMM1 for jj=0 ---
        #pragma unroll
        for (int v = 0; v < 4; v++)
            #pragma unroll
            for (int u = 0; u < 4; u++) Scur[v][u] = 0.f;
        #pragma unroll
        for (int kk = 0; kk < 4; kk++) {
            uint2 Bx = *(const uint2*)&KsW[0 * 8 * SROW + kk * 16];
            uint2 By = *(const uint2*)&KsW[1 * 8 * SROW + kk * 16];
            mma_bf16(Scur[0], Qa[kk][0], Qa[kk][1], Qa[kk][2], Qa[kk][3], Bx.x, Bx.y);
            mma_bf16(Scur[1], Qa[kk][4], Qa[kk][5], Qa[kk][6], Qa[kk][7], Bx.x, Bx.y);
            mma_bf16(Scur[2], Qa[kk][0], Qa[kk][1], Qa[kk][2], Qa[kk][3], By.x, By.y);
            mma_bf16(Scur[3], Qa[kk][4], Qa[kk][5], Qa[kk][6], Qa[kk][7], By.x, By.y);
        }

        #pragma unroll
        for (int jj = 0; jj < 4; jj++) {
            // ---- exp (in place) + sums + pack A-fragments for GEMM2(jj) ----
            #pragma unroll
            for (int v = 0; v < 4; v++)
                #pragma unroll
                for (int u = 0; u < 4; u++) Scur[v][u] = ex2(Scur[v][u]);
            sum0 += Scur[0][0] + Scur[0][1] + Scur[2][0] + Scur[2][1];  // tile0 row g
            sum1 += Scur[0][2] + Scur[0][3] + Scur[2][2] + Scur[2][3];  // tile0 row g+8
            sum2 += Scur[1][0] + Scur[1][1] + Scur[3][0] + Scur[3][1];  // tile1 row g
            sum3 += Scur[1][2] + Scur[1][3] + Scur[3][2] + Scur[3][3];  // tile1 row g+8
            uint32_t a0 = pack_bf2(Scur[0][0], Scur[0][1]), a1 = pack_bf2(Scur[0][2], Scur[0][3]);
            uint32_t a2 = pack_bf2(Scur[2][0], Scur[2][1]), a3 = pack_bf2(Scur[2][2], Scur[2][3]);
            uint32_t a4 = pack_bf2(Scur[1][0], Scur[1][1]), a5 = pack_bf2(Scur[1][2], Scur[1][3]);
            uint32_t a6 = pack_bf2(Scur[3][0], Scur[3][1]), a7 = pack_bf2(Scur[3][2], Scur[3][3]);

            if (jj < 3) {
                // ---- fused: GEMM1(jj+1) interleaved with GEMM2(jj) ----
                #pragma unroll
                for (int v = 0; v < 4; v++)
                    #pragma unroll
                    for (int u = 0; u < 4; u++) Snxt[v][u] = 0.f;
                #pragma unroll
                for (int u = 0; u < 4; u++) {
                    uint2 Bx = *(const uint2*)&KsW[(2 * (jj + 1)    ) * 8 * SROW + u * 16];
                    uint2 By = *(const uint2*)&KsW[(2 * (jj + 1) + 1) * 8 * SROW + u * 16];
                    mma_bf16(Snxt[0], Qa[u][0], Qa[u][1], Qa[u][2], Qa[u][3], Bx.x, Bx.y);
                    mma_bf16(Snxt[1], Qa[u][4], Qa[u][5], Qa[u][6], Qa[u][7], Bx.x, Bx.y);
                    mma_bf16(Snxt[2], Qa[u][0], Qa[u][1], Qa[u][2], Qa[u][3], By.x, By.y);
                    mma_bf16(Snxt[3], Qa[u][4], Qa[u][5], Qa[u][6], Qa[u][7], By.x, By.y);
                    uint2 Bv0 = *(const uint2*)&VsW[(2 * u    ) * 8 * SROW + jj * 16];
                    uint2 Bv1 = *(const uint2*)&VsW[(2 * u + 1) * 8 * SROW + jj * 16];
                    mma_bf16(O0[2 * u    ], a0, a1, a2, a3, Bv0.x, Bv0.y);
                    mma_bf16(O1[2 * u    ], a4, a5, a6, a7, Bv0.x, Bv0.y);
                    mma_bf16(O0[2 * u + 1], a0, a1, a2, a3, Bv1.x, Bv1.y);
                    mma_bf16(O1[2 * u + 1], a4, a5, a6, a7, Bv1.x, Bv1.y);
                }
                #pragma unroll
                for (int v = 0; v < 4; v++)
                    #pragma unroll
                    for (int u = 0; u < 4; u++) Scur[v][u] = Snxt[v][u];
            } else {
                // ---- epilogue of chunk: GEMM2(3) only ----
                #pragma unroll
                for (int j = 0; j < 8; j++) {
                    uint2 Bv = *(const uint2*)&VsW[j * 8 * SROW + jj * 16];
                    mma_bf16(O0[j], a0, a1, a2, a3, Bv.x, Bv.y);
                    mma_bf16(O1[j], a4, a5, a6, a7, Bv.x, Bv.y);
                }
            }
        }
        __syncthreads();   // all warps done reading chunk-c tiles
    }

    // quad-reduce row sums (lanes 4g..4g+3 share rows)
    sum0 += __shfl_xor_sync(0xffffffffu, sum0, 1);
    sum0 += __shfl_xor_sync(0xffffffffu, sum0, 2);
    sum1 += __shfl_xor_sync(0xffffffffu, sum1, 1);
    sum1 += __shfl_xor_sync(0xffffffffu, sum1, 2);
    sum2 += __shfl_xor_sync(0xffffffffu, sum2, 1);
    sum2 += __shfl_xor_sync(0xffffffffu, sum2, 2);
    sum3 += __shfl_xor_sync(0xffffffffu, sum3, 1);
    sum3 += __shfl_xor_sync(0xffffffffu, sum3, 2);
    const float i0 = 1.f / sum0, i1 = 1.f / sum1, i2 = 1.f / sum2, i3 = 1.f / sum3;

    const float* Vb = V + (size_t)bh * SEQ * DIM;
    float* Ob = Out + (size_t)bh * SEQ * DIM;
    const size_t r0 = wrow + g, r1 = r0 + 8, r2 = r0 + 16, r3 = r0 + 24;
    #pragma unroll
    for (int j = 0; j < 8; j++) {
        int cix = j * 8 + 2 * t4;
        float2 v0 = *(const float2*)&Vb[r0 * DIM + cix];
        float2 v1 = *(const float2*)&Vb[r1 * DIM + cix];
        float2 v2 = *(const float2*)&Vb[r2 * DIM + cix];
        float2 v3 = *(const float2*)&Vb[r3 * DIM + cix];
        *(float2*)&Ob[r0 * DIM + cix] = make_float2(O0[j][0] * i0 + v0.x, O0[j][1] * i0 + v0.y);
        *(float2*)&Ob[r1 * DIM + cix] = make_float2(O0[j][2] * i1 + v1.x, O0[j][3] * i1 + v1.y);
        *(float2*)&Ob[r2 * DIM + cix] = make_float2(O1[j][0] * i2 + v2.x, O1[j][1] * i2 + v2.y);
        *(float2*)&Ob[r3 * DIM + cix] = make_float2(O1[j][2] * i3 + v3.x, O1[j][3] * i3 + v3.y);
    }
}

extern "C" void kernel_launch(void* const* d_in, const int* in_sizes, int n_in,
                              void* d_out, int out_size) {
    const float* Q = (const float*)d_in[0];
    const float* K = (const float*)d_in[1];
    const float* V = (const float*)d_in[2];
    float*       O = (float*)d_out;

    const int smem = 2 * KVSZ * (int)sizeof(__nv_bfloat16);   // 40960 B
    cudaFuncSetAttribute(attn_kernel, cudaFuncAttributeMaxDynamicSharedMemorySize, smem);

    sketch_kernel<<<dim3(B_H, 8, 2), 256>>>(K, V);
    attn_kernel<<<dim3(SEQ / 128, B_H), 128, smem>>>(Q, V, O);
}

// round 17
// speedup vs baseline: 1.0918x; 1.0746x over previous
#include <cuda_runtime.h>
#include <cuda_bf16.h>
#include <cstdint>

// Problem constants (B=4, H=16, N=4096, D=64, M2=512, N/M2=8)
#define B_H   64
#define SEQ   4096
#define DIM   64
#define M2C   512
#define SROW  80    // smem row stride in bf16; 160B stride -> conflict-free LDS.64 frags

// Scratch sketches in bf16, 1/8 scale pre-applied, contraction dim pair-interleaved:
// within each 16-elem k-group, pair p=(k>>1)&7 sits at phys pair 2*(p&3)+(p>>2),
// so a thread's (k=2t4, k=2t4+8) fragment pairs are adjacent -> one LDS.64.
__device__ __nv_bfloat16 g_sks[B_H * M2C * DIM];   // [bh][m'][a~]
__device__ __nv_bfloat16 g_stv[B_H * DIM * M2C];   // [bh][e][m'~]

__device__ __forceinline__ float ex2(float x) {
    float y; asm("ex2.approx.f32 %0, %1;" : "=f"(y) : "f"(x)); return y;
}
__device__ __forceinline__ uint32_t pack_bf2(float lo, float hi) {
    __nv_bfloat162 h = __floats2bfloat162_rn(lo, hi);
    return *(uint32_t*)&h;
}
__device__ __forceinline__ void mma_bf16(float c[4],
        uint32_t a0, uint32_t a1, uint32_t a2, uint32_t a3,
        uint32_t b0, uint32_t b1) {
    asm volatile(
        "mma.sync.aligned.m16n8k16.row.col.f32.bf16.bf16.f32 "
        "{%0,%1,%2,%3}, {%4,%5,%6,%7}, {%8,%9}, {%0,%1,%2,%3};\n"
        : "+f"(c[0]), "+f"(c[1]), "+f"(c[2]), "+f"(c[3])
        : "r"(a0), "r"(a1), "r"(a2), "r"(a3), "r"(b0), "r"(b1));
}
__device__ __forceinline__ void cpa16(uint32_t s, const void* g) {
    asm volatile("cp.async.cg.shared.global [%0], [%1], 16;" :: "r"(s), "l"(g));
}

// ---------------------------------------------------------------------------
// Kernel 1: build sketches, m' = r*64 + d permutation (softmax-invariant; the
// same permutation is applied to SKS and STV so the result is exact).
//   SKS_P[m'][a~] = (1/8) sum_j K[r*512 + j*64 + a][d]     (z = 0)
//   STV_P[e][m'~] = (1/8) sum_j V[(d*8+r)*8 + j][e]        (z = 1)
// Split across blockIdx.z so the two 64MB streams run concurrently.
// ---------------------------------------------------------------------------
__global__ __launch_bounds__(256) void sketch_kernel(const float* __restrict__ K,
                                                     const float* __restrict__ V) {
    __shared__ float acc[64 * 65];
    const int bh = blockIdx.x, r = blockIdx.y;
    const int tid = threadIdx.x;

    if (blockIdx.z == 0) {
        const float* Kb = K + (size_t)bh * SEQ * DIM;
        __nv_bfloat16* sks = g_sks + (size_t)bh * M2C * DIM;
        for (int l = tid; l < 1024; l += 256) {
            int a = l >> 4, d4 = (l & 15) << 2;
            float4 s = make_float4(0.f, 0.f, 0.f, 0.f);
            #pragma unroll
            for (int j = 0; j < 8; j++) {
                float4 x = *(const float4*)&Kb[(r * 512 + j * 64 + a) * 64 + d4];
                s.x += x.x; s.y += x.y; s.z += x.z; s.w += x.w;
            }
            float* dst = &acc[a * 65 + d4];
            dst[0] = s.x; dst[1] = s.y; dst[2] = s.z; dst[3] = s.w;
        }
        __syncthreads();
        for (int l = tid; l < 2048; l += 256) {       // pair p covers a=2p,2p+1
            int d = l >> 5, p = l & 31;
            float lo = acc[(2 * p    ) * 65 + d] * 0.125f;
            float hi = acc[(2 * p + 1) * 65 + d] * 0.125f;
            int q = p & 7;
            int phys = ((p >> 3) << 4) + ((2 * (q & 3) + (q >> 2)) << 1);
            *(uint32_t*)&sks[(r * 64 + d) * 64 + phys] = pack_bf2(lo, hi);
        }
    } else {
        const float* Vb = V + (size_t)bh * SEQ * DIM;
        __nv_bfloat16* stv = g_stv + (size_t)bh * DIM * M2C;
        for (int l = tid; l < 1024; l += 256) {
            int d = l >> 4, e4 = (l & 15) << 2;
            float4 s = make_float4(0.f, 0.f, 0.f, 0.f);
            #pragma unroll
            for (int j = 0; j < 8; j++) {
                float4 x = *(const float4*)&Vb[((d * 8 + r) * 8 + j) * 64 + e4];
                s.x += x.x; s.y += x.y; s.z += x.z; s.w += x.w;
            }
            float* dst = &acc[d * 65 + e4];
            dst[0] = s.x; dst[1] = s.y; dst[2] = s.z; dst[3] = s.w;
        }
        __syncthreads();
        for (int l = tid; l < 2048; l += 256) {       // pair p covers d=2p,2p+1
            int e = l >> 5, p = l & 31;
            float lo = acc[(2 * p    ) * 65 + e] * 0.125f;
            float hi = acc[(2 * p + 1) * 65 + e] * 0.125f;
            int q = p & 7;
            int phys = ((p >> 3) << 4) + ((2 * (q & 3) + (q >> 2)) << 1);
            *(uint32_t*)&stv[e * 512 + r * 64 + phys] = pack_bf2(lo, hi);
        }
    }
}

// ---------------------------------------------------------------------------
// Kernel 2: out = softmax(Q SKS^T / 8) @ STV + V  via bf16 m16n8k16 mma.sync.
// 128 threads (4 warps); warp owns 32 query rows. 8 chunks of 64 sketch cols,
// double-buffered cp.async pipeline (R8 structure, best measured). P never
// leaves registers (GEMM1 C-frag pair == GEMM2 A-frag of k-group jj).
// NEW: softmax row sums computed ON THE TENSOR PIPE — an extra n8 MMA per
// tile per jj with a constant all-ones B fragment accumulates sum_m P[n,m]
// into Osum (each row's sum lands replicated across its quad: no FADD chain,
// no epilogue shuffles). exp via MUFU.EX2 (log2e/8 folded into Q).
// ---------------------------------------------------------------------------
#define KVSZ (2 * 64 * SROW)    // one Ks+Vs buffer, in bf16 elems
#define ONES_BF16X2 0x3F803F80u // bf16 {1.0, 1.0}

__global__ __launch_bounds__(128, 3) void attn_kernel(const float* __restrict__ Q,
                                                      const float* __restrict__ V,
                                                      float* __restrict__ Out) {
    extern __shared__ __align__(16) char smb[];
    __nv_bfloat16* kvbuf = (__nv_bfloat16*)smb;              // [2][KVSZ]

    const int tid  = threadIdx.x;
    const int lane = tid & 31, warp = tid >> 5;
    const int g = lane >> 2, t4 = lane & 3;
    const int bh   = blockIdx.y;
    const int wrow = blockIdx.x * 128 + warp * 32;

    const float* Qb = Q + (size_t)bh * SEQ * DIM;
    const __nv_bfloat16* sksb = g_sks + (size_t)bh * M2C * DIM;
    const __nv_bfloat16* stvb = g_stv + (size_t)bh * DIM * M2C;

    auto stage = [&](int c, __nv_bfloat16* buf) {
        __nv_bfloat16* Kd = buf;
        __nv_bfloat16* Vd = buf + 64 * SROW;
        const int mc0 = c * 64;
        #pragma unroll
        for (int i = 0; i < 4; i++) {
            int l = tid + i * 128;
            int row = l >> 3, seg = (l & 7) * 8;
            cpa16((uint32_t)__cvta_generic_to_shared(&Kd[row * SROW + seg]),
                  &sksb[(mc0 + row) * 64 + seg]);
            cpa16((uint32_t)__cvta_generic_to_shared(&Vd[row * SROW + seg]),
                  &stvb[row * 512 + mc0 + seg]);
        }
        asm volatile("cp.async.commit_group;");
    };

    // Persistent Q fragments (both 16-row tiles); scale 0.125*log2(e) folded.
    const float qs = 0.125f * 1.4426950408889634f;
    uint32_t Qa[4][8];
    #pragma unroll
    for (int tt = 0; tt < 2; tt++) {
        const float* q0 = Qb + (size_t)(wrow + tt * 16 + g) * DIM;
        const float* q1 = Qb + (size_t)(wrow + tt * 16 + g + 8) * DIM;
        #pragma unroll
        for (int kk = 0; kk < 4; kk++) {
            float2 x0 = *(const float2*)&q0[kk * 16 + 2 * t4];
            float2 x1 = *(const float2*)&q1[kk * 16 + 2 * t4];
            float2 x2 = *(const float2*)&q0[kk * 16 + 2 * t4 + 8];
            float2 x3 = *(const float2*)&q1[kk * 16 + 2 * t4 + 8];
            Qa[kk][tt * 4 + 0] = pack_bf2(x0.x * qs, x0.y * qs);
            Qa[kk][tt * 4 + 1] = pack_bf2(x1.x * qs, x1.y * qs);
            Qa[kk][tt * 4 + 2] = pack_bf2(x2.x * qs, x2.y * qs);
            Qa[kk][tt * 4 + 3] = pack_bf2(x3.x * qs, x3.y * qs);
        }
    }

    float O0[8][4], O1[8][4];
    #pragma unroll
    for (int j = 0; j < 8; j++)
        #pragma unroll
        for (int c = 0; c < 4; c++) { O0[j][c] = 0.f; O1[j][c] = 0.f; }
    float Osum0[4] = {0,0,0,0}, Osum1[4] = {0,0,0,0};   // P @ ones (row sums)

    stage(0, kvbuf);    // prologue: chunk 0 -> buffer 0

    for (int c = 0; c < 8; c++) {
        __nv_bfloat16* Ks = kvbuf + (c & 1) * KVSZ;
        __nv_bfloat16* Vs = Ks + 64 * SROW;

        if (c + 1 < 8) {
            stage(c + 1, kvbuf + ((c + 1) & 1) * KVSZ);
            asm volatile("cp.async.wait_group 1;");
        } else {
            asm volatile("cp.async.wait_group 0;");
        }
        __syncthreads();   // chunk-c tiles visible to all warps

        const __nv_bfloat16* KsW = Ks + g * SROW + 4 * t4;   // hoisted frag bases
        const __nv_bfloat16* VsW = Vs + g * SROW + 4 * t4;

        #pragma unroll
        for (int jj = 0; jj < 4; jj++) {
            // ---- GEMM1: logits for j-pair (2jj, 2jj+1), both 16-row tiles ----
            float Sa[4] = {0,0,0,0}, Sb[4] = {0,0,0,0};   // tile0/tile1, col j0
            float Sc[4] = {0,0,0,0}, Sd[4] = {0,0,0,0};   // tile0/tile1, col j1
            #pragma unroll
            for (int kk = 0; kk < 4; kk++) {
                uint2 Bx = *(const uint2*)&KsW[(2 * jj    ) * 8 * SROW + kk * 16];
                uint2 By = *(const uint2*)&KsW[(2 * jj + 1) * 8 * SROW + kk * 16];
                mma_bf16(Sa, Qa[kk][0], Qa[kk][1], Qa[kk][2], Qa[kk][3], Bx.x, Bx.y);
                mma_bf16(Sb, Qa[kk][4], Qa[kk][5], Qa[kk][6], Qa[kk][7], Bx.x, Bx.y);
                mma_bf16(Sc, Qa[kk][0], Qa[kk][1], Qa[kk][2], Qa[kk][3], By.x, By.y);
                mma_bf16(Sd, Qa[kk][4], Qa[kk][5], Qa[kk][6], Qa[kk][7], By.x, By.y);
            }
            // ---- exp (in place) + pack: C-frag (j0,j1) == A-frag of GEMM2 jj ----
            #pragma unroll
            for (int u = 0; u < 4; u++) {
                Sa[u] = ex2(Sa[u]); Sb[u] = ex2(Sb[u]);
                Sc[u] = ex2(Sc[u]); Sd[u] = ex2(Sd[u]);
            }
            uint32_t a0 = pack_bf2(Sa[0], Sa[1]), a1 = pack_bf2(Sa[2], Sa[3]);
            uint32_t a2 = pack_bf2(Sc[0], Sc[1]), a3 = pack_bf2(Sc[2], Sc[3]);
            uint32_t a4 = pack_bf2(Sb[0], Sb[1]), a5 = pack_bf2(Sb[2], Sb[3]);
            uint32_t a6 = pack_bf2(Sd[0], Sd[1]), a7 = pack_bf2(Sd[2], Sd[3]);
            // ---- row sums on the tensor pipe: Osum += P(:, jj) @ ones ----
            mma_bf16(Osum0, a0, a1, a2, a3, ONES_BF16X2, ONES_BF16X2);
            mma_bf16(Osum1, a4, a5, a6, a7, ONES_BF16X2, ONES_BF16X2);
            // ---- GEMM2 partial: O += P(:, kk=jj) @ STV(kk=jj, :) ----
            #pragma unroll
            for (int j = 0; j < 8; j++) {
                uint2 Bv = *(const uint2*)&VsW[j * 8 * SROW + jj * 16];
                mma_bf16(O0[j], a0, a1, a2, a3, Bv.x, Bv.y);
                mma_bf16(O1[j], a4, a5, a6, a7, Bv.x, Bv.y);
            }
        }
        __syncthreads();   // all warps done reading chunk-c tiles
    }

    // Row sums arrive replicated across each quad: no shuffles needed.
    const float i0 = 1.f / Osum0[0];   // tile0 row g
    const float i1 = 1.f / Osum0[2];   // tile0 row g+8
    const float i2 = 1.f / Osum1[0];   // tile1 row g
    const float i3 = 1.f / Osum1[2];   // tile1 row g+8

    const float* Vb = V + (size_t)bh * SEQ * DIM;
    float* Ob = Out + (size_t)bh * SEQ * DIM;
    const size_t r0 = wrow + g, r1 = r0 + 8, r2 = r0 + 16, r3 = r0 + 24;
    #pragma unroll
    for (int j = 0; j < 8; j++) {
        int cix = j * 8 + 2 * t4;
        float2 v0 = *(const float2*)&Vb[r0 * DIM + cix];
        float2 v1 = *(const float2*)&Vb[r1 * DIM + cix];
        float2 v2 = *(const float2*)&Vb[r2 * DIM + cix];
        float2 v3 = *(const float2*)&Vb[r3 * DIM + cix];
        *(float2*)&Ob[r0 * DIM + cix] = make_float2(O0[j][0] * i0 + v0.x, O0[j][1] * i0 + v0.y);
        *(float2*)&Ob[r1 * DIM + cix] = make_float2(O0[j][2] * i1 + v1.x, O0[j][3] * i1 + v1.y);
        *(float2*)&Ob[r2 * DIM + cix] = make_float2(O1[j][0] * i2 + v2.x, O1[j][1] * i2 + v2.y);
        *(float2*)&Ob[r3 * DIM + cix] = make_float2(O1[j][2] * i3 + v3.x, O1[j][3] * i3 + v3.y);
    }
}

extern "C" void kernel_launch(void* const* d_in, const int* in_sizes, int n_in,
                              void* d_out, int out_size) {
    const float* Q = (const float*)d_in[0];
    const float* K = (const float*)d_in[1];
    const float* V = (const float*)d_in[2];
    float*       O = (float*)d_out;

    const int smem = 2 * KVSZ * (int)sizeof(__nv_bfloat16);   // 40960 B
    cudaFuncSetAttribute(attn_kernel, cudaFuncAttributeMaxDynamicSharedMemorySize, smem);

    sketch_kernel<<<dim3(B_H, 8, 2), 256>>>(K, V);
    attn_kernel<<<dim3(SEQ / 128, B_H), 128, smem>>>(Q, V, O);
}